// round 1
// baseline (speedup 1.0000x reference)
#include <cuda_runtime.h>
#include <cuda_bf16.h>

// Problem constants
#define D      1024
#define L      16384
#define LF     32768
#define T      128          // chunk length
#define NC     (L / T)      // 128 chunks
#define EPSV   1e-4f

// Scratch (static device allocations are allowed)
__device__ float g_B[NC * D];      // chunk-final local state
__device__ float g_Zpre[NC * D];   // state entering each chunk
__device__ float g_A[NC];          // per-chunk decay product
__device__ int   g_pos[L + 1];     // boundary positions + sentinel

// ---------------------------------------------------------------------------
// K0: scan of b (LF int32) -> pos[s] = index of s-th one; pos[L] = LF
// Single block, 1024 threads, 32 elements each.
// ---------------------------------------------------------------------------
__global__ void k_scan_b(const int* __restrict__ b) {
    __shared__ int warp_tot[32];
    const int tid  = threadIdx.x;
    const int lane = tid & 31;
    const int wid  = tid >> 5;
    const int base = tid * 32;

    int loc[32];
    // vectorized load: 8 x int4
    const int4* b4 = (const int4*)(b + base);
    #pragma unroll
    for (int i = 0; i < 8; i++) {
        int4 v = b4[i];
        loc[i * 4 + 0] = v.x; loc[i * 4 + 1] = v.y;
        loc[i * 4 + 2] = v.z; loc[i * 4 + 3] = v.w;
    }
    int s = 0;
    #pragma unroll
    for (int i = 0; i < 32; i++) s += loc[i];

    // warp inclusive scan of per-thread sums
    int incl = s;
    #pragma unroll
    for (int off = 1; off < 32; off <<= 1) {
        int v = __shfl_up_sync(0xffffffffu, incl, off);
        if (lane >= off) incl += v;
    }
    if (lane == 31) warp_tot[wid] = incl;
    __syncthreads();
    if (wid == 0) {
        int w = warp_tot[lane];
        int wi = w;
        #pragma unroll
        for (int off = 1; off < 32; off <<= 1) {
            int v = __shfl_up_sync(0xffffffffu, wi, off);
            if (lane >= off) wi += v;
        }
        warp_tot[lane] = wi - w;   // exclusive warp prefix
    }
    __syncthreads();
    int excl = warp_tot[wid] + (incl - s);  // exclusive prefix for this thread

    int run = excl;
    #pragma unroll
    for (int i = 0; i < 32; i++) {
        if (loc[i]) { g_pos[run] = base + i; run++; }
    }
    if (tid == 0) g_pos[L] = LF;
}

// ---------------------------------------------------------------------------
// K1: per-chunk local scan. One block per chunk; 256 threads x 4 channels.
// Produces g_B[c][d] (final local state, z_{-1}=0) and g_A[c] (prod of decay).
// ---------------------------------------------------------------------------
__global__ __launch_bounds__(256) void k_chunk_local(
    const float* __restrict__ x, const float* __restrict__ p) {
    __shared__ float sa[T];   // decay  (1-p)
    __shared__ float sb[T];   // input coeff (p)
    const int c   = blockIdx.x;
    const int tid = threadIdx.x;
    const int t0  = c * T;

    if (tid < T) {
        float pv = p[t0 + tid];
        pv = fminf(fmaxf(pv, EPSV), 1.0f - EPSV);
        sa[tid] = 1.0f - pv;
        sb[tid] = pv;
    }
    __syncthreads();

    float z0 = 0.f, z1 = 0.f, z2 = 0.f, z3 = 0.f;
    const float* xr = x + (size_t)t0 * D + tid;
    #pragma unroll 4
    for (int t = 0; t < T; t++) {
        float a = sa[t], pb = sb[t];
        const float* row = xr + (size_t)t * D;
        z0 = a * z0 + pb * row[0];
        z1 = a * z1 + pb * row[256];
        z2 = a * z2 + pb * row[512];
        z3 = a * z3 + pb * row[768];
    }
    float* Bo = g_B + (size_t)c * D + tid;
    Bo[0] = z0; Bo[256] = z1; Bo[512] = z2; Bo[768] = z3;

    if (tid == 0) {
        float A = 1.0f;
        #pragma unroll
        for (int t = 0; t < T; t++) A *= sa[t];
        g_A[c] = A;
    }
}

// ---------------------------------------------------------------------------
// K2: chunk-level prefix scan. One thread per channel, serial over NC chunks.
// g_Zpre[c][d] = state entering chunk c.
// ---------------------------------------------------------------------------
__global__ __launch_bounds__(128) void k_chunk_prefix() {
    __shared__ float sA[NC];
    const int tid = threadIdx.x;
    const int ch  = blockIdx.x * 128 + tid;
    for (int i = tid; i < NC; i += 128) sA[i] = g_A[i];
    __syncthreads();

    float z = 0.f;
    for (int c = 0; c < NC; c++) {
        g_Zpre[(size_t)c * D + ch] = z;
        z = sA[c] * z + g_B[(size_t)c * D + ch];
    }
}

// ---------------------------------------------------------------------------
// K3: re-scan each chunk with injected prefix state and scatter each z row
// to output rows [pos[s], pos[s+1]).
// ---------------------------------------------------------------------------
__global__ __launch_bounds__(256) void k_rescan_scatter(
    const float* __restrict__ x, const float* __restrict__ p,
    float* __restrict__ out) {
    __shared__ float sa[T];
    __shared__ float sb[T];
    __shared__ int   spos[T + 1];
    const int c   = blockIdx.x;
    const int tid = threadIdx.x;
    const int t0  = c * T;

    if (tid < T) {
        float pv = p[t0 + tid];
        pv = fminf(fmaxf(pv, EPSV), 1.0f - EPSV);
        sa[tid] = 1.0f - pv;
        sb[tid] = pv;
    }
    if (tid <= T) spos[tid] = g_pos[t0 + tid];
    __syncthreads();

    const float* Zp = g_Zpre + (size_t)c * D + tid;
    float z0 = Zp[0], z1 = Zp[256], z2 = Zp[512], z3 = Zp[768];

    const float* xr = x + (size_t)t0 * D + tid;
    for (int t = 0; t < T; t++) {
        float a = sa[t], pb = sb[t];
        const float* row = xr + (size_t)t * D;
        z0 = a * z0 + pb * row[0];
        z1 = a * z1 + pb * row[256];
        z2 = a * z2 + pb * row[512];
        z3 = a * z3 + pb * row[768];

        int ps = spos[t], pe = spos[t + 1];
        for (int r = ps; r < pe; r++) {
            float* o = out + (size_t)r * D + tid;
            o[0] = z0; o[256] = z1; o[512] = z2; o[768] = z3;
        }
    }
}

// ---------------------------------------------------------------------------
extern "C" void kernel_launch(void* const* d_in, const int* in_sizes, int n_in,
                              void* d_out, int out_size) {
    const float* x = (const float*)d_in[0];
    const float* p = (const float*)d_in[1];
    const int*   b = (const int*)d_in[2];
    float* out = (float*)d_out;

    k_scan_b<<<1, 1024>>>(b);
    k_chunk_local<<<NC, 256>>>(x, p);
    k_chunk_prefix<<<D / 128, 128>>>();
    k_rescan_scatter<<<NC, 256>>>(x, p, out);
}

// round 4
// speedup vs baseline: 2.2045x; 2.2045x over previous
#include <cuda_runtime.h>
#include <cuda_bf16.h>

// Problem constants
#define D      1024
#define DV     (D / 4)      // 256 float4 lanes
#define L      16384
#define LF     32768
#define T      64           // chunk length
#define NC     (L / T)      // 256 chunks
#define NG     16           // chunk groups
#define GS     (NC / NG)    // 16 chunks per group
#define EPSV   1e-4f

// Scratch (__device__ globals; no dynamic allocation allowed)
__device__ float4 g_B4[NC * DV];     // chunk-final local state
__device__ float4 g_Zpre4[NC * DV];  // group-LOCAL prefix entering each chunk
__device__ float4 g_Bg4[NG * DV];    // group-final local state
__device__ float4 g_Zg4[NG * DV];    // state entering each group
__device__ float  g_A[NC];           // per-chunk decay product
__device__ float  g_cumA[NC];        // prod of A within group, [group_start, c)
__device__ float  g_Ag[NG];          // per-group decay product
__device__ int    g_pos[L + 1];      // boundary positions + sentinel

// ---------------------------------------------------------------------------
// K0: scan of b (LF int32) -> pos[s] = index of s-th one; pos[L] = LF
// ---------------------------------------------------------------------------
__global__ void k_scan_b(const int* __restrict__ b) {
    __shared__ int warp_tot[32];
    const int tid  = threadIdx.x;
    const int lane = tid & 31;
    const int wid  = tid >> 5;
    const int base = tid * 32;

    int loc[32];
    const int4* b4 = (const int4*)(b + base);
    #pragma unroll
    for (int i = 0; i < 8; i++) {
        int4 v = b4[i];
        loc[i * 4 + 0] = v.x; loc[i * 4 + 1] = v.y;
        loc[i * 4 + 2] = v.z; loc[i * 4 + 3] = v.w;
    }
    int s = 0;
    #pragma unroll
    for (int i = 0; i < 32; i++) s += loc[i];

    int incl = s;
    #pragma unroll
    for (int off = 1; off < 32; off <<= 1) {
        int v = __shfl_up_sync(0xffffffffu, incl, off);
        if (lane >= off) incl += v;
    }
    if (lane == 31) warp_tot[wid] = incl;
    __syncthreads();
    if (wid == 0) {
        int w = warp_tot[lane];
        int wi = w;
        #pragma unroll
        for (int off = 1; off < 32; off <<= 1) {
            int v = __shfl_up_sync(0xffffffffu, wi, off);
            if (lane >= off) wi += v;
        }
        warp_tot[lane] = wi - w;
    }
    __syncthreads();
    int run = warp_tot[wid] + (incl - s);
    #pragma unroll
    for (int i = 0; i < 32; i++) {
        if (loc[i]) { g_pos[run] = base + i; run++; }
    }
    if (tid == 0) g_pos[L] = LF;
}

// ---------------------------------------------------------------------------
// K1: per-chunk local scan, float4 per thread, 8-row load batches.
// ---------------------------------------------------------------------------
__global__ __launch_bounds__(DV) void k_chunk_local(
    const float* __restrict__ x, const float* __restrict__ p) {
    __shared__ float sa[T];
    __shared__ float sb[T];
    const int c   = blockIdx.x;
    const int tid = threadIdx.x;

    if (tid < T) {
        float pv = __ldg(p + c * T + tid);
        pv = fminf(fmaxf(pv, EPSV), 1.0f - EPSV);
        sa[tid] = 1.0f - pv;
        sb[tid] = pv;
    }
    __syncthreads();

    const float4* xr = (const float4*)x + (size_t)c * T * DV + tid;
    float4 z = make_float4(0.f, 0.f, 0.f, 0.f);

    for (int tb = 0; tb < T; tb += 8) {
        float4 v[8];
        #pragma unroll
        for (int i = 0; i < 8; i++) v[i] = __ldg(xr + (size_t)(tb + i) * DV);
        #pragma unroll
        for (int i = 0; i < 8; i++) {
            float a = sa[tb + i], pb = sb[tb + i];
            z.x = a * z.x + pb * v[i].x;
            z.y = a * z.y + pb * v[i].y;
            z.z = a * z.z + pb * v[i].z;
            z.w = a * z.w + pb * v[i].w;
        }
    }
    g_B4[(size_t)c * DV + tid] = z;

    if (tid == 0) {
        float A = 1.0f;
        #pragma unroll
        for (int t = 0; t < T; t++) A *= sa[t];
        g_A[c] = A;
    }
}

// ---------------------------------------------------------------------------
// K2a: group-local chunk prefix. One block per group of 16 chunks.
// Writes group-LOCAL Zpre, per-chunk cumA (within group), and group (Ag, Bg).
// ---------------------------------------------------------------------------
__global__ __launch_bounds__(DV) void k_group_local() {
    __shared__ float sA[GS];
    const int g   = blockIdx.x;
    const int tid = threadIdx.x;
    if (tid < GS) sA[tid] = g_A[g * GS + tid];
    __syncthreads();

    float4 z = make_float4(0.f, 0.f, 0.f, 0.f);
    float  Acum = 1.0f;
    #pragma unroll
    for (int j = 0; j < GS; j++) {
        const int c = g * GS + j;
        g_Zpre4[(size_t)c * DV + tid] = z;
        if (tid == 0) g_cumA[c] = Acum;
        float a = sA[j];
        float4 Bv = g_B4[(size_t)c * DV + tid];
        z.x = a * z.x + Bv.x;
        z.y = a * z.y + Bv.y;
        z.z = a * z.z + Bv.z;
        z.w = a * z.w + Bv.w;
        Acum *= a;
    }
    g_Bg4[(size_t)g * DV + tid] = z;
    if (tid == 0) g_Ag[g] = Acum;
}

// ---------------------------------------------------------------------------
// K2b: serial scan over 16 groups. One block.
// ---------------------------------------------------------------------------
__global__ __launch_bounds__(DV) void k_group_scan() {
    __shared__ float sAg[NG];
    const int tid = threadIdx.x;
    if (tid < NG) sAg[tid] = g_Ag[tid];
    __syncthreads();

    float4 z = make_float4(0.f, 0.f, 0.f, 0.f);
    #pragma unroll
    for (int g = 0; g < NG; g++) {
        g_Zg4[(size_t)g * DV + tid] = z;
        float a = sAg[g];
        float4 Bv = g_Bg4[(size_t)g * DV + tid];
        z.x = a * z.x + Bv.x;
        z.y = a * z.y + Bv.y;
        z.z = a * z.z + Bv.z;
        z.w = a * z.w + Bv.w;
    }
}

// ---------------------------------------------------------------------------
// K3: re-scan with injected prefix (group-local + cumA*groupState), scatter
// each z row to output rows [pos[s], pos[s+1]) with float4 stores.
// ---------------------------------------------------------------------------
__global__ __launch_bounds__(DV) void k_rescan_scatter(
    const float* __restrict__ x, const float* __restrict__ p,
    float* __restrict__ out) {
    __shared__ float sa[T];
    __shared__ float sb[T];
    __shared__ int   spos[T + 1];
    const int c   = blockIdx.x;
    const int tid = threadIdx.x;

    if (tid < T) {
        float pv = __ldg(p + c * T + tid);
        pv = fminf(fmaxf(pv, EPSV), 1.0f - EPSV);
        sa[tid] = 1.0f - pv;
        sb[tid] = pv;
    }
    if (tid <= T) spos[tid] = g_pos[c * T + tid];
    __syncthreads();

    // z_pre(c) = Zpre_local(c) + cumA(c) * Zg(group(c))
    float  ca = g_cumA[c];
    float4 zl = g_Zpre4[(size_t)c * DV + tid];
    float4 zg = g_Zg4[(size_t)(c / GS) * DV + tid];
    float4 z;
    z.x = zl.x + ca * zg.x;
    z.y = zl.y + ca * zg.y;
    z.z = zl.z + ca * zg.z;
    z.w = zl.w + ca * zg.w;

    const float4* xr   = (const float4*)x + (size_t)c * T * DV + tid;
    float4*       out4 = (float4*)out;

    for (int tb = 0; tb < T; tb += 8) {
        float4 v[8];
        #pragma unroll
        for (int i = 0; i < 8; i++) v[i] = __ldg(xr + (size_t)(tb + i) * DV);
        #pragma unroll
        for (int i = 0; i < 8; i++) {
            const int t = tb + i;
            float a = sa[t], pb = sb[t];
            z.x = a * z.x + pb * v[i].x;
            z.y = a * z.y + pb * v[i].y;
            z.z = a * z.z + pb * v[i].z;
            z.w = a * z.w + pb * v[i].w;
            const int ps = spos[t], pe = spos[t + 1];
            for (int r = ps; r < pe; r++)
                out4[(size_t)r * DV + tid] = z;
        }
    }
}

// ---------------------------------------------------------------------------
extern "C" void kernel_launch(void* const* d_in, const int* in_sizes, int n_in,
                              void* d_out, int out_size) {
    const float* x = (const float*)d_in[0];
    const float* p = (const float*)d_in[1];
    const int*   b = (const int*)d_in[2];
    float* out = (float*)d_out;

    k_scan_b<<<1, 1024>>>(b);
    k_chunk_local<<<NC, DV>>>(x, p);
    k_group_local<<<NG, DV>>>();
    k_group_scan<<<1, DV>>>();
    k_rescan_scatter<<<NC, DV>>>(x, p, out);
}